// round 6
// baseline (speedup 1.0000x reference)
#include <cuda_runtime.h>

// SSIM loss: 1 - mean(ssim_map(clean, adv)), 11x11 gaussian sigma=1.5, zero SAME padding.
// d_in[0]=clean [32,3,512,512] f32, d_in[1]=adversarial. Output: 1 float.
//
// Persistent y-strip design: each block owns a 32-wide x 256-tall strip and
// sweeps down in 32-row chunks, keeping a 42-row ring of horizontal-pass
// intermediates in smem so each horizontal row is computed exactly once.

#define IMG 512
#define TILE_X 32
#define HALO 5
#define EXT_X 42
#define STRIP 256
#define CHUNK 32
#define NCHUNK 8
#define RING 42
#define NPIX (32.0 * 3.0 * 512.0 * 512.0)
#define NBLOCKS (16 * 2 * 96)

typedef unsigned long long u64;

__device__ double g_ssim_acc = 0.0;
__device__ unsigned int g_done = 0;

// ---- packed f32x2 helpers (ptxas will not emit FFMA2 from C++) ----
__device__ __forceinline__ u64 pack2(float x, float y) {
    u64 r; asm("mov.b64 %0, {%1, %2};" : "=l"(r) : "f"(x), "f"(y)); return r;
}
__device__ __forceinline__ float2 un2(u64 v) {
    float2 r; asm("mov.b64 {%0, %1}, %2;" : "=f"(r.x), "=f"(r.y) : "l"(v)); return r;
}
__device__ __forceinline__ u64 fma2(u64 a, u64 b, u64 c) {
    u64 d; asm("fma.rn.f32x2 %0, %1, %2, %3;" : "=l"(d) : "l"(a), "l"(b), "l"(c)); return d;
}
__device__ __forceinline__ u64 mul2(u64 a, u64 b) {
    u64 d; asm("mul.rn.f32x2 %0, %1, %2;" : "=l"(d) : "l"(a), "l"(b)); return d;
}
__device__ __forceinline__ u64 add2(u64 a, u64 b) {
    u64 d; asm("add.rn.f32x2 %0, %1, %2;" : "=l"(d) : "l"(a), "l"(b)); return d;
}

// Gaussian window, sigma=1.5, 11 taps, normalized.
#define W0 0.26601173f
#define W1 0.21300555f
#define W2 0.10936069f
#define W3 0.03600077f
#define W4 0.00759875f
#define W5 0.00102838f

__global__ void __launch_bounds__(256, 5) ssim_strip_kernel(
    const float* __restrict__ clean, const float* __restrict__ adv,
    float* __restrict__ out)
{
    __shared__ u64 s_raw[CHUNK][EXT_X];    // chunk raw rows (packed)    10752 B
    __shared__ u64 s_mu[RING][TILE_X];     // ring: (m1, m2)             10752 B
    __shared__ u64 s_sq[RING][TILE_X];     // ring: (s11, s22)           10752 B
    __shared__ float s_xx[RING][TILE_X];   // ring: s12                   5376 B
    __shared__ float s_red[8];

    const float wf[11] = {W5, W4, W3, W2, W1, W0, W1, W2, W3, W4, W5};
    const u64 p0 = pack2(W0, W0), p1 = pack2(W1, W1), p2 = pack2(W2, W2);
    const u64 p3 = pack2(W3, W3), p4 = pack2(W4, W4), p5 = pack2(W5, W5);
    const u64 wp[11] = {p5, p4, p3, p2, p1, p0, p1, p2, p3, p4, p5};

    const int plane = blockIdx.z;
    const float* cp = clean + (size_t)plane * IMG * IMG;
    const float* ap = adv   + (size_t)plane * IMG * IMG;
    const int x0 = blockIdx.x * TILE_X;
    const int S  = blockIdx.y * STRIP;
    const int tid = threadIdx.x;
    const int tx = tid & 31;
    const int ty = tid >> 5;

    float local = 0.f;

    // Phase 0: prologue rows [S-5, S+5). Phase p>=1: chunk p-1 — horizontal
    // rows [Y+5, Y+37) then vertical outputs [Y, Y+32), Y = S + 32*(p-1).
    for (int p = 0; p <= NCHUNK; p++) {
        int rlo = (p == 0) ? ((S == 0) ? 0 : S - HALO)
                           : S + CHUNK * (p - 1) + HALO;
        int rhi = (p == 0) ? (S + HALO)
                           : S + CHUNK * (p - 1) + CHUNK + HALO;
        if (rhi > IMG) rhi = IMG;
        const int nr = rhi - rlo;

        // ---- raw rows -> s_raw (zero x-padding) ----
        for (int idx = tid; idx < nr * EXT_X; idx += 256) {
            int i = idx / EXT_X;
            int c = idx - i * EXT_X;
            int gy = rlo + i;
            int gx = x0 - HALO + c;
            float cv = 0.f, av = 0.f;
            if ((unsigned)gx < IMG) {
                cv = cp[gy * IMG + gx];
                av = ap[gy * IMG + gx];
            }
            s_raw[i][c] = pack2(cv, av);
        }
        __syncthreads();

        // ---- horizontal pass into the ring ----
        for (int idx = tid; idx < (nr << 5); idx += 256) {
            int i = idx >> 5, c = idx & 31;
            const u64* row = &s_raw[i][c];
            u64 m = 0ull, s = 0ull;
            float x12 = 0.f;
            #pragma unroll
            for (int k = 0; k < 11; k++) {
                u64 v = row[k];
                u64 t = mul2(wp[k], v);      // (w*x, w*y)
                m = add2(m, t);              // (mu1, mu2)
                s = fma2(t, v, s);           // (E x^2, E y^2)
                float2 tv = un2(t);
                float2 vv = un2(v);
                x12 = fmaf(tv.x, vv.y, x12); // E xy
            }
            int slot = (unsigned)(rlo + i) % RING;
            s_mu[slot][c] = m;
            s_sq[slot][c] = s;
            s_xx[slot][c] = x12;
        }
        __syncthreads();

        // ---- vertical pass + epilogue for chunk p-1 ----
        if (p >= 1) {
            const int Y = S + CHUNK * (p - 1);
            const int rbase = Y + ty * 4;      // 4 consecutive output rows
            u64 am[4] = {0ull, 0ull, 0ull, 0ull};
            u64 ae[4] = {0ull, 0ull, 0ull, 0ull};
            float a12[4] = {0.f, 0.f, 0.f, 0.f};

            #pragma unroll
            for (int j = 0; j < 15; j++) {
                int r = rbase + j - HALO;
                u64 mu = 0ull, sq = 0ull;
                float xx = 0.f;
                if ((unsigned)r < IMG) {       // zero y-padding outside image
                    int slot = (unsigned)r % RING;
                    mu = s_mu[slot][tx];
                    sq = s_sq[slot][tx];
                    xx = s_xx[slot][tx];
                }
                #pragma unroll
                for (int o = 0; o < 4; o++) {
                    const int k = j - o;
                    if (k >= 0 && k <= 10) {
                        am[o] = fma2(wp[k], mu, am[o]);
                        ae[o] = fma2(wp[k], sq, ae[o]);
                        a12[o] = fmaf(wf[k], xx, a12[o]);
                    }
                }
            }

            const float C1 = 1.0e-4f;
            const float C2 = 9.0e-4f;
            #pragma unroll
            for (int o = 0; o < 4; o++) {
                float2 m = un2(am[o]);
                float2 e = un2(ae[o]);
                float mu1_sq = m.x * m.x;
                float mu2_sq = m.y * m.y;
                float mu12   = m.x * m.y;
                float sig1  = e.x - mu1_sq;
                float sig2  = e.y - mu2_sq;
                float sig12 = a12[o] - mu12;
                float num = (2.f * mu12 + C1) * (2.f * sig12 + C2);
                float den = (mu1_sq + mu2_sq + C1) * (sig1 + sig2 + C2);
                local += __fdividef(num, den);
            }
        }
        __syncthreads();   // protect ring + s_raw before next phase's writes
    }

    // ---- block reduction ----
    #pragma unroll
    for (int off = 16; off > 0; off >>= 1)
        local += __shfl_down_sync(0xFFFFFFFFu, local, off);
    if (tx == 0) s_red[ty] = local;
    __syncthreads();
    if (tid == 0) {
        float bs = 0.f;
        #pragma unroll
        for (int i = 0; i < 8; i++) bs += s_red[i];
        atomicAdd(&g_ssim_acc, (double)bs);
        __threadfence();
        unsigned t = atomicAdd(&g_done, 1u);
        if (t == NBLOCKS - 1) {
            // last block: finalize, then reset for the next graph replay
            double acc = atomicAdd(&g_ssim_acc, 0.0);
            out[0] = 1.0f - (float)(acc / NPIX);
            g_done = 0;
            g_ssim_acc = 0.0;
        }
    }
}

extern "C" void kernel_launch(void* const* d_in, const int* in_sizes, int n_in,
                              void* d_out, int out_size) {
    const float* clean = (const float*)d_in[0];
    const float* adv   = (const float*)d_in[1];
    float* out = (float*)d_out;

    dim3 grid(IMG / TILE_X, IMG / STRIP, 96);   // 16 x 2 x 96 = 3072 blocks
    ssim_strip_kernel<<<grid, 256>>>(clean, adv, out);
}

// round 7
// speedup vs baseline: 1.1841x; 1.1841x over previous
#include <cuda_runtime.h>

// SSIM loss: 1 - mean(ssim_map(clean, adv)), 11x11 gaussian sigma=1.5, zero SAME padding.
// d_in[0]=clean [32,3,512,512] f32, d_in[1]=adversarial. Output: 1 float.
//
// Y-strip sweep (32 wide x 256 tall per block) with a 42-row ring of
// horizontal-pass intermediates. All ring indexing is incremental (no %
// in hot loops), task maps are static, vertical is templated on boundary.

#define IMG 512
#define HALO 5
#define EXT_X 42
#define RING 42
#define STRIP 256
#define CHUNK 32
#define NPHASE 8
#define NPIX (32.0 * 3.0 * 512.0 * 512.0)
#define NBLOCKS (16 * 2 * 96)

typedef unsigned long long u64;

__device__ double g_ssim_acc = 0.0;
__device__ unsigned int g_done = 0;

__device__ __forceinline__ u64 pack2(float x, float y) {
    u64 r; asm("mov.b64 %0, {%1, %2};" : "=l"(r) : "f"(x), "f"(y)); return r;
}
__device__ __forceinline__ float2 un2(u64 v) {
    float2 r; asm("mov.b64 {%0, %1}, %2;" : "=f"(r.x), "=f"(r.y) : "l"(v)); return r;
}
__device__ __forceinline__ u64 fma2(u64 a, u64 b, u64 c) {
    u64 d; asm("fma.rn.f32x2 %0, %1, %2, %3;" : "=l"(d) : "l"(a), "l"(b), "l"(c)); return d;
}
__device__ __forceinline__ u64 mul2(u64 a, u64 b) {
    u64 d; asm("mul.rn.f32x2 %0, %1, %2;" : "=l"(d) : "l"(a), "l"(b)); return d;
}
__device__ __forceinline__ u64 add2(u64 a, u64 b) {
    u64 d; asm("add.rn.f32x2 %0, %1, %2;" : "=l"(d) : "l"(a), "l"(b)); return d;
}

#define W0 0.26601173f
#define W1 0.21300555f
#define W2 0.10936069f
#define W3 0.03600077f
#define W4 0.00759875f
#define W5 0.00102838f

struct Acc { u64 am[4]; u64 ae[4]; float a12[4]; };

// Vertical accumulate + epilogue. TOP/BOT select the (rare) guarded versions.
template<bool TOP, bool BOT>
__device__ __forceinline__ float vertical_pass(
    const float4 (*s_msq)[32], const float (*s_xx)[32],
    int vs_base, int Y, int tx, int ty, const u64* wp, const float* wf)
{
    const int rbase = 4 * ty;                 // local output row 0..28
    int s = vs_base + rbase;
    if (s >= RING) s -= RING;

    u64 am[4] = {0ull, 0ull, 0ull, 0ull};
    u64 ae[4] = {0ull, 0ull, 0ull, 0ull};
    float a12[4] = {0.f, 0.f, 0.f, 0.f};

    #pragma unroll
    for (int j = 0; j < 15; j++) {
        float4 q;
        float xx;
        bool valid = true;
        if (TOP) valid = (rbase + j >= HALO);          // global row >= 0
        if (BOT) valid = (Y + rbase + j - HALO < IMG); // global row < 512
        if (valid) {
            q = s_msq[s][tx];
            xx = s_xx[s][tx];
        } else {
            q = make_float4(0.f, 0.f, 0.f, 0.f);
            xx = 0.f;
        }
        u64 mu = pack2(q.x, q.y);
        u64 sq = pack2(q.z, q.w);
        #pragma unroll
        for (int o = 0; o < 4; o++) {
            const int k = j - o;
            if (k >= 0 && k <= 10) {
                am[o] = fma2(wp[k], mu, am[o]);
                ae[o] = fma2(wp[k], sq, ae[o]);
                a12[o] = fmaf(wf[k], xx, a12[o]);
            }
        }
        s++; if (s >= RING) s -= RING;
    }

    const float C1 = 1.0e-4f;
    const float C2 = 9.0e-4f;
    float local = 0.f;
    #pragma unroll
    for (int o = 0; o < 4; o++) {
        float2 m = un2(am[o]);
        float2 e = un2(ae[o]);
        float mu1_sq = m.x * m.x;
        float mu2_sq = m.y * m.y;
        float mu12   = m.x * m.y;
        float sig1  = e.x - mu1_sq;
        float sig2  = e.y - mu2_sq;
        float sig12 = a12[o] - mu12;
        float num = (2.f * mu12 + C1) * (2.f * sig12 + C2);
        float den = (mu1_sq + mu2_sq + C1) * (sig1 + sig2 + C2);
        local += __fdividef(num, den);
    }
    return local;
}

__global__ void __launch_bounds__(256, 5) ssim_strip_kernel(
    const float* __restrict__ clean, const float* __restrict__ adv,
    float* __restrict__ out)
{
    __shared__ u64    s_raw[CHUNK][EXT_X];   // packed (x, y)          10752 B
    __shared__ float4 s_msq[RING][32];       // (m1, m2, s11, s22)     21504 B
    __shared__ float  s_xx[RING][32];        // s12                     5376 B
    __shared__ float  s_red[8];

    const float wf[11] = {W5, W4, W3, W2, W1, W0, W1, W2, W3, W4, W5};
    const u64 p0 = pack2(W0, W0), p1 = pack2(W1, W1), p2 = pack2(W2, W2);
    const u64 p3 = pack2(W3, W3), p4 = pack2(W4, W4), p5 = pack2(W5, W5);
    const u64 wp[11] = {p5, p4, p3, p2, p1, p0, p1, p2, p3, p4, p5};

    const int plane = blockIdx.z;
    const float* cp = clean + (size_t)plane * IMG * IMG;
    const float* ap = adv   + (size_t)plane * IMG * IMG;
    const int x0 = blockIdx.x * 32;
    const int S  = blockIdx.y * STRIP;
    const int tid = threadIdx.x;
    const int tx = tid & 31;
    const int ty = tid >> 5;

    // raw-load walker start (one division, once)
    const int lr0 = tid / EXT_X;
    const int lc0 = tid - lr0 * EXT_X;

    float local = 0.f;

    // ---- prologue: horizontal rows [max(S-5,0), S+5) into the ring ----
    {
        const int rlo = (S == 0) ? 0 : (S - HALO);
        const int nr = S + HALO - rlo;              // 5 or 10
        for (int idx = tid; idx < nr * EXT_X; idx += 256) {
            int i = idx / EXT_X, c = idx - i * EXT_X;
            int gx = x0 - HALO + c;
            float cv = 0.f, av = 0.f;
            if ((unsigned)gx < IMG) {
                int g = (rlo + i) * IMG + gx;
                cv = cp[g]; av = ap[g];
            }
            s_raw[i][c] = pack2(cv, av);
        }
        __syncthreads();
        const int ps0 = rlo % RING;
        #pragma unroll
        for (int it = 0; it < 2; it++) {
            int i = ty + 8 * it;
            if (i < nr) {
                const u64* row = &s_raw[i][tx];
                u64 m = 0ull, s = 0ull;
                float x12 = 0.f;
                #pragma unroll
                for (int k = 0; k < 11; k++) {
                    u64 v = row[k];
                    u64 t = mul2(wp[k], v);
                    m = add2(m, t);
                    s = fma2(t, v, s);
                    float2 tv = un2(t); float2 vv = un2(v);
                    x12 = fmaf(tv.x, vv.y, x12);
                }
                int slot = ps0 + i; if (slot >= RING) slot -= RING;
                float2 mm = un2(m), ss = un2(s);
                s_msq[slot][tx] = make_float4(mm.x, mm.y, ss.x, ss.y);
                s_xx[slot][tx] = x12;
            }
        }
        __syncthreads();
    }

    int hs_base = (S + HALO) % RING;          // slot of first horiz row, phase 1
    int vs_base = (S + RING - HALO) % RING;   // slot of row S-5 (mod), phase 1

    for (int p = 1; p <= NPHASE; p++) {
        const int rl = S + CHUNK * (p - 1) + HALO;   // first horiz row this phase
        int nr = CHUNK;
        if (rl + nr > IMG) nr = IMG - rl;            // 27 on the last phase

        // ---- raw rows [rl, rl+nr) -> s_raw (incremental walker) ----
        {
            int r = lr0, c = lc0;
            #pragma unroll
            for (int it = 0; it < 6; it++) {
                if (r < nr) {
                    int gx = x0 - HALO + c;
                    float cv = 0.f, av = 0.f;
                    if ((unsigned)gx < IMG) {
                        int g = (rl + r) * IMG + gx;
                        cv = cp[g]; av = ap[g];
                    }
                    s_raw[r][c] = pack2(cv, av);
                }
                r += 6; c += 4;
                if (c >= EXT_X) { c -= EXT_X; r += 1; }
            }
        }
        __syncthreads();

        // ---- horizontal: warp-per-row, 4 static iterations ----
        #pragma unroll
        for (int it = 0; it < 4; it++) {
            int i = ty + 8 * it;
            if (i < nr) {
                const u64* row = &s_raw[i][tx];
                u64 m = 0ull, s = 0ull;
                float x12 = 0.f;
                #pragma unroll
                for (int k = 0; k < 11; k++) {
                    u64 v = row[k];
                    u64 t = mul2(wp[k], v);
                    m = add2(m, t);
                    s = fma2(t, v, s);
                    float2 tv = un2(t); float2 vv = un2(v);
                    x12 = fmaf(tv.x, vv.y, x12);
                }
                int slot = hs_base + i; if (slot >= RING) slot -= RING;
                float2 mm = un2(m), ss = un2(s);
                s_msq[slot][tx] = make_float4(mm.x, mm.y, ss.x, ss.y);
                s_xx[slot][tx] = x12;
            }
        }
        __syncthreads();

        // ---- vertical + epilogue for output rows [Y, Y+32) ----
        const int Y = S + CHUNK * (p - 1);
        if (Y == 0)
            local += vertical_pass<true, false>(s_msq, s_xx, vs_base, Y, tx, ty, wp, wf);
        else if (Y + CHUNK + HALO > IMG)
            local += vertical_pass<false, true>(s_msq, s_xx, vs_base, Y, tx, ty, wp, wf);
        else
            local += vertical_pass<false, false>(s_msq, s_xx, vs_base, Y, tx, ty, wp, wf);

        hs_base += CHUNK; if (hs_base >= RING) hs_base -= RING;
        vs_base += CHUNK; if (vs_base >= RING) vs_base -= RING;
        __syncthreads();   // ring reuse protection before next phase writes
    }

    // ---- block reduction + single-pass finalize ----
    #pragma unroll
    for (int off = 16; off > 0; off >>= 1)
        local += __shfl_down_sync(0xFFFFFFFFu, local, off);
    if (tx == 0) s_red[ty] = local;
    __syncthreads();
    if (tid == 0) {
        float bs = 0.f;
        #pragma unroll
        for (int i = 0; i < 8; i++) bs += s_red[i];
        atomicAdd(&g_ssim_acc, (double)bs);
        __threadfence();
        unsigned t = atomicAdd(&g_done, 1u);
        if (t == NBLOCKS - 1) {
            double acc = atomicAdd(&g_ssim_acc, 0.0);
            out[0] = 1.0f - (float)(acc / NPIX);
            g_done = 0;
            g_ssim_acc = 0.0;
        }
    }
}

extern "C" void kernel_launch(void* const* d_in, const int* in_sizes, int n_in,
                              void* d_out, int out_size) {
    const float* clean = (const float*)d_in[0];
    const float* adv   = (const float*)d_in[1];
    float* out = (float*)d_out;

    dim3 grid(IMG / 32, IMG / STRIP, 96);   // 16 x 2 x 96 = 3072 blocks
    ssim_strip_kernel<<<grid, 256>>>(clean, adv, out);
}